// round 4
// baseline (speedup 1.0000x reference)
#include <cuda_runtime.h>

// PCEN transform, exact two-phase chunked scan.
// x: (B=64, T=4000, F=128) fp32.  out same shape.
// Phase 1: per-(b,f) EMA over full T, storing exact checkpoints M[c*CHUNK-1].
// Phase 2: 16 T-chunks in parallel per (b,f), each resuming from its checkpoint,
//          computing out = sqrt(x*(M+eps)^(-alpha) + delta) - sqrt(delta).

#define B_LEN  64
#define T_LEN  4000
#define F_LEN  128
#define CHUNK  250
#define NCHUNK 16          // T_LEN / CHUNK

#define C_S        0.025f
#define C_1MS      0.975f
#define C_EPS      1e-6f
#define C_NALPHA  (-0.98f)
#define C_DELTA    2.0f
#define C_SQRTD    1.41421356237309515f

// Exact EMA checkpoints M[c*CHUNK - 1] for c = 1..NCHUNK-1.  480 KB static scratch.
__device__ float g_ckpt[(NCHUNK - 1) * B_LEN * F_LEN];

__device__ __forceinline__ float f_lg2(float x) {
    float r; asm("lg2.approx.f32 %0, %1;" : "=f"(r) : "f"(x)); return r;
}
__device__ __forceinline__ float f_ex2(float x) {
    float r; asm("ex2.approx.f32 %0, %1;" : "=f"(r) : "f"(x)); return r;
}
__device__ __forceinline__ float f_sqrt(float x) {
    float r; asm("sqrt.approx.f32 %0, %1;" : "=f"(r) : "f"(x)); return r;
}

// -------- Phase 1: sequential EMA, store checkpoints --------
// grid: (B_LEN), block: (F_LEN).  One thread per (b, f) chain.
__global__ void __launch_bounds__(F_LEN)
pcen_phase1(const float* __restrict__ x) {
    const int b = blockIdx.x;
    const int f = threadIdx.x;
    const float* p = x + (b * T_LEN) * F_LEN + f;

    float m = p[0];                    // M[0] = x[0]
    int t = 1;
    for (int seg = 1; seg < NCHUNK; ++seg) {
        const int tend = seg * CHUNK;
        #pragma unroll 8
        for (; t < tend; ++t) {
            m = fmaf(C_1MS, m, C_S * p[t * F_LEN]);
        }
        g_ckpt[((seg - 1) * B_LEN + b) * F_LEN + f] = m;   // M[seg*CHUNK - 1]
    }
}

// -------- Phase 2: parallel chunks, full PCEN math --------
// grid: (NCHUNK, B_LEN), block: (F_LEN).
__global__ void __launch_bounds__(F_LEN)
pcen_phase2(const float* __restrict__ x, float* __restrict__ out) {
    const int c = blockIdx.x;
    const int b = blockIdx.y;
    const int f = threadIdx.x;

    const int base = (b * T_LEN + c * CHUNK) * F_LEN + f;
    const float* px = x + base;
    float* po = out + base;

    float m;
    if (c == 0) {
        // M state just before t=0 chosen so first update yields M[0]=x[0]:
        // 0.975*x0 + 0.025*x0 = x0.
        m = px[0];
    } else {
        m = g_ckpt[((c - 1) * B_LEN + b) * F_LEN + f];     // M[c*CHUNK - 1]
    }

    #pragma unroll 4
    for (int i = 0; i < CHUNK; ++i) {
        const float xv = px[i * F_LEN];
        m = fmaf(C_1MS, m, C_S * xv);                      // M[t]
        const float a = m + C_EPS;
        // x * (M+eps)^(-alpha)  ==  x * exp2(-alpha * log2(M+eps))  (no division)
        const float e = f_ex2(C_NALPHA * f_lg2(a));
        const float v = fmaf(xv, e, C_DELTA);
        po[i * F_LEN] = f_sqrt(v) - C_SQRTD;
    }
}

extern "C" void kernel_launch(void* const* d_in, const int* in_sizes, int n_in,
                              void* d_out, int out_size) {
    const float* x = (const float*)d_in[0];
    float* out = (float*)d_out;
    (void)in_sizes; (void)n_in; (void)out_size;

    pcen_phase1<<<B_LEN, F_LEN>>>(x);
    pcen_phase2<<<dim3(NCHUNK, B_LEN), F_LEN>>>(x, out);
}

// round 5
// speedup vs baseline: 2.9356x; 2.9356x over previous
#include <cuda_runtime.h>

// PCEN transform via exact linear-recurrence chunk decomposition.
// x: (B=64, T=4000, F=128) fp32, out same shape.
//
//   M[t] = a*M[t-1] + s*x[t],  a = 0.975, s = 0.025,  M[0] = x[0]
//   out  = sqrt(x * (M+eps)^(-alpha) + delta) - sqrt(delta)
//
// Pass 1 (parallel): per-chunk local EMA c_k (zero initial state; chunk 0 real).
// Pass 2 (tiny):     ckpt_k = a^L * ckpt_{k-1} + c_k  (31 serial FMAs per chain).
// Pass 3 (parallel): per-chunk output sweep resuming from exact checkpoint.
// a^125 ~= 0.042, so cross-chunk rounding decays geometrically.

#define B_LEN  64
#define T_LEN  4000
#define F_LEN  128
#define F4     (F_LEN / 4)       // 32 float4 lanes per row
#define CHUNK  125
#define NCHUNK 32                // T_LEN / CHUNK

#define C_S        0.025f
#define C_1MS      0.975f
#define C_EPS      1e-6f
#define C_NALPHA  (-0.98f)
#define C_DELTA    2.0f
#define C_SQRTD    1.41421356237309515f

// Scratch: chunk-local partial EMAs [b][c][f] and checkpoints [b][c-1][f].
__device__ float4 g_local[B_LEN * NCHUNK * F4];        // 1 MB
__device__ float4 g_ckpt [B_LEN * (NCHUNK - 1) * F4];  // ~1 MB

__device__ __forceinline__ float f_lg2(float v) {
    float r; asm("lg2.approx.f32 %0, %1;" : "=f"(r) : "f"(v)); return r;
}
__device__ __forceinline__ float f_ex2(float v) {
    float r; asm("ex2.approx.f32 %0, %1;" : "=f"(r) : "f"(v)); return r;
}
__device__ __forceinline__ float f_sqrt(float v) {
    float r; asm("sqrt.approx.f32 %0, %1;" : "=f"(r) : "f"(v)); return r;
}

// ---- Pass 1: chunk-local EMA partials (fully parallel) ----
// 512 blocks x 128 threads; each warp owns one (b, c) pair, float4 per lane.
__global__ void __launch_bounds__(128)
pcen_local(const float4* __restrict__ x4) {
    const int p    = blockIdx.x * 4 + (threadIdx.x >> 5);   // pair id = b*NCHUNK + c
    const int lane = threadIdx.x & 31;
    const int c    = p & (NCHUNK - 1);
    const int b    = p >> 5;

    const float4* px = x4 + (size_t)(b * T_LEN + c * CHUNK) * F4 + lane;

    float4 m;
    int i0;
    if (c == 0) {                 // real initial state: M[0] = x[0]
        m = px[0];
        i0 = 1;
    } else {                      // zero-state local partial
        m = make_float4(0.f, 0.f, 0.f, 0.f);
        i0 = 0;
    }

    #pragma unroll 5
    for (int i = i0; i < CHUNK; ++i) {
        const float4 xv = px[(size_t)i * F4];
        m.x = fmaf(C_1MS, m.x, C_S * xv.x);
        m.y = fmaf(C_1MS, m.y, C_S * xv.y);
        m.z = fmaf(C_1MS, m.z, C_S * xv.z);
        m.w = fmaf(C_1MS, m.w, C_S * xv.w);
    }
    g_local[p * F4 + lane] = m;
}

// ---- Pass 2: serial combine across chunks (tiny) ----
// 2048 threads total; each owns one (b, f4) chain, 31 FMAs.
__global__ void __launch_bounds__(256)
pcen_combine() {
    const int tid  = blockIdx.x * blockDim.x + threadIdx.x;   // 0..2047
    if (tid >= B_LEN * F4) return;
    const int b    = tid >> 5;
    const int lane = tid & 31;

    // a^CHUNK in double for accuracy (cost irrelevant in this tiny kernel).
    double ad = 1.0;
    for (int i = 0; i < CHUNK; ++i) ad *= 0.975;
    const float aL = (float)ad;

    float4 m = g_local[(b * NCHUNK + 0) * F4 + lane];          // true M[CHUNK-1]
    g_ckpt[(b * (NCHUNK - 1) + 0) * F4 + lane] = m;            // ckpt for chunk 1
    #pragma unroll
    for (int k = 1; k < NCHUNK - 1; ++k) {
        const float4 lk = g_local[(b * NCHUNK + k) * F4 + lane];
        m.x = fmaf(aL, m.x, lk.x);
        m.y = fmaf(aL, m.y, lk.y);
        m.z = fmaf(aL, m.z, lk.z);
        m.w = fmaf(aL, m.w, lk.w);
        g_ckpt[(b * (NCHUNK - 1) + k) * F4 + lane] = m;        // ckpt for chunk k+1
    }
}

// ---- Pass 3: output sweep per chunk, resuming from exact checkpoint ----
// 512 blocks x 128 threads, same (b, c)-per-warp mapping as pass 1.
__global__ void __launch_bounds__(128)
pcen_out(const float4* __restrict__ x4, float4* __restrict__ out4) {
    const int p    = blockIdx.x * 4 + (threadIdx.x >> 5);
    const int lane = threadIdx.x & 31;
    const int c    = p & (NCHUNK - 1);
    const int b    = p >> 5;

    const size_t base = (size_t)(b * T_LEN + c * CHUNK) * F4 + lane;
    const float4* px = x4 + base;
    float4*       po = out4 + base;

    float4 m;
    if (c == 0) {
        // Pre-state chosen so first update yields M[0]=x[0]: a*x0 + s*x0 = x0.
        m = px[0];
    } else {
        m = g_ckpt[(b * (NCHUNK - 1) + (c - 1)) * F4 + lane];  // M[c*CHUNK - 1]
    }

    #pragma unroll 4
    for (int i = 0; i < CHUNK; ++i) {
        const float4 xv = px[(size_t)i * F4];
        float4 o;

        m.x = fmaf(C_1MS, m.x, C_S * xv.x);
        m.y = fmaf(C_1MS, m.y, C_S * xv.y);
        m.z = fmaf(C_1MS, m.z, C_S * xv.z);
        m.w = fmaf(C_1MS, m.w, C_S * xv.w);

        o.x = f_sqrt(fmaf(xv.x, f_ex2(C_NALPHA * f_lg2(m.x + C_EPS)), C_DELTA)) - C_SQRTD;
        o.y = f_sqrt(fmaf(xv.y, f_ex2(C_NALPHA * f_lg2(m.y + C_EPS)), C_DELTA)) - C_SQRTD;
        o.z = f_sqrt(fmaf(xv.z, f_ex2(C_NALPHA * f_lg2(m.z + C_EPS)), C_DELTA)) - C_SQRTD;
        o.w = f_sqrt(fmaf(xv.w, f_ex2(C_NALPHA * f_lg2(m.w + C_EPS)), C_DELTA)) - C_SQRTD;

        po[(size_t)i * F4] = o;
    }
}

extern "C" void kernel_launch(void* const* d_in, const int* in_sizes, int n_in,
                              void* d_out, int out_size) {
    const float4* x4 = (const float4*)d_in[0];
    float4* out4 = (float4*)d_out;
    (void)in_sizes; (void)n_in; (void)out_size;

    const int pairs = B_LEN * NCHUNK;           // 2048 warps
    pcen_local  <<<pairs / 4, 128>>>(x4);
    pcen_combine<<<(B_LEN * F4 + 255) / 256, 256>>>();
    pcen_out    <<<pairs / 4, 128>>>(x4, out4);
}